// round 15
// baseline (speedup 1.0000x reference)
#include <cuda_runtime.h>
#include <math.h>

// ---------------------------------------------------------------------------
// Problem constants (fixed by the dataset generator)
// ---------------------------------------------------------------------------
#define PP   1000003u          // prime modulus
#define NN   1000002u          // group order p-1 = 2*3*166667
#define BATCH 4
#define NPATCH 784
#define LVEC 9
#define KKER 16
#define NPIX (BATCH * NPATCH)        // 3136
#define TOTAL (KKER * NPIX)          // 50176
#define DRANGE 9000
#define TSIZE (2 * DRANGE + 1)       // 18001

// prep work partition (thread-id ranges)
#define TCHUNKS ((TSIZE + 7) / 8)            // 2251 dlog-chain threads
#define CCHUNKS (NPIX * LVEC / 8)            // 3528 cts batch-inverse threads
#define PREP_B_END (TCHUNKS + CCHUNKS)       // 5779
#define PREP_C_END (PREP_B_END + NPIX)       // 8915

// ---------------------------------------------------------------------------
// Montgomery constants (compile time)
// ---------------------------------------------------------------------------
constexpr unsigned nprime_f() {            // -p^{-1} mod 2^32 (Newton)
    unsigned inv = PP;
    for (int i = 0; i < 5; i++) inv *= 2u - PP * inv;
    return 0u - inv;
}
constexpr unsigned onem_f() { return (unsigned)((1ULL << 32) % PP); }
constexpr unsigned r2_f() {
    return (unsigned)(((unsigned long long)onem_f() * onem_f()) % PP);
}
constexpr unsigned NPRIME = nprime_f();
constexpr unsigned ONEM   = onem_f();
constexpr unsigned R2M    = r2_f();

// ---------------------------------------------------------------------------
// Scratch (device globals; no dynamic allocation anywhere)
// ---------------------------------------------------------------------------
__device__ int      g_dlog[1000003];
__device__ unsigned g_ctsM[LVEC * NPIX];
__device__ unsigned g_ctsInvM[LVEC * NPIX];
__device__ unsigned g_c0pow[20 * NPIX];          // ct0^(2^j), [j][pixel]
__device__ __align__(16) float g_feat1[BATCH * KKER * NPATCH];
__device__ __align__(16) float g_x2[BATCH * 32 * 7 * 7];
__device__ __align__(16) float g_x3[BATCH * 64 * 3 * 3];
__device__ unsigned g_done = 0;                  // conv3 completion ticket

// ---------------------------------------------------------------------------
// Montgomery multiply: a,b in Mont domain (< p); result < p.
// ---------------------------------------------------------------------------
__device__ __forceinline__ unsigned mm(unsigned a, unsigned b) {
    unsigned long long T = (unsigned long long)a * b;
    unsigned m = (unsigned)T * NPRIME;
    unsigned long long t = (T + (unsigned long long)m * PP) >> 32;
    unsigned r = (unsigned)t;
    return (r >= PP) ? r - PP : r;
}

__device__ __forceinline__ unsigned powM(unsigned b, unsigned e) {
    unsigned r = ONEM;
    while (e) {
        if (e & 1u) r = mm(r, b);
        b = mm(b, b);
        e >>= 1;
    }
    return r;
}

__device__ __forceinline__ unsigned powM20(unsigned b, unsigned e) {
    unsigned r = ONEM;
#pragma unroll
    for (int i = 0; i < 20; i++) {
        if ((e >> i) & 1u) r = mm(r, b);
        b = mm(b, b);
    }
    return r;
}

// ---------------------------------------------------------------------------
// Input layout detection (int32 / int64 / float32), from ct0 buffer.
// ---------------------------------------------------------------------------
__device__ __forceinline__ int detect_layout(const void* ct0) {
    const unsigned* u = (const unsigned*)ct0;
    unsigned w0 = u[0];
    if (w0 >= 1u && w0 < PP) {
        if (u[1] == 0u && u[3] == 0u && u[5] == 0u) return 1;  // int64
        return 0;                                              // int32
    }
    return 2;                                                  // float32
}

__device__ __forceinline__ long long ld_int(const void* ptr, int idx, int lay) {
    if (lay == 0) return (long long)((const int*)ptr)[idx];
    if (lay == 1) return ((const long long*)ptr)[idx];
    return (long long)llrintf(((const float*)ptr)[idx]);
}

// ---------------------------------------------------------------------------
// K0: prep — chained dlog table + batch-inverted Mont cts + ct0 pow2 table
// ---------------------------------------------------------------------------
__global__ void k_prep(const void* ct0, const void* cts, const void* gptr) {
    int gid = blockIdx.x * blockDim.x + threadIdx.x;
    int lay = detect_layout(ct0);
    if (gid < TCHUNKS) {
        // A: dlog table, 8 chained entries per thread (1 pow + 7 muls)
        unsigned g  = (unsigned)ld_int(gptr, 0, lay) % PP;
        unsigned gM = mm(g, R2M);
        int te0 = gid * 8;
        int e0  = te0 - DRANGE;
        unsigned ee = (e0 < 0) ? (unsigned)(e0 + (int)NN) : (unsigned)e0;
        unsigned v = powM(gM, ee);
#pragma unroll
        for (int j = 0; j < 8; j++) {
            int te = te0 + j;
            if (te < TSIZE) g_dlog[v] = te - DRANGE;
            v = mm(v, gM);
        }
    } else if (gid < PREP_B_END) {
        // B: cts -> Mont + batch inversion (Montgomery trick), 8 per thread
        int i0 = (gid - TCHUNKS) * 8;
        unsigned c[8], pfx[8];
#pragma unroll
        for (int j = 0; j < 8; j++)
            c[j] = mm((unsigned)ld_int(cts, i0 + j, lay), R2M);
        pfx[0] = c[0];
#pragma unroll
        for (int j = 1; j < 8; j++) pfx[j] = mm(pfx[j - 1], c[j]);
        unsigned inv = powM20(pfx[7], PP - 2u);      // one Fermat for 8 items
#pragma unroll
        for (int j = 7; j >= 1; j--) {
            unsigned invj = mm(inv, pfx[j - 1]);
            inv = mm(inv, c[j]);
            int idx = i0 + j, pix = idx / LVEC, ii = idx - pix * LVEC;
            g_ctsM[ii * NPIX + pix]    = c[j];
            g_ctsInvM[ii * NPIX + pix] = invj;
        }
        { int idx = i0, pix = idx / LVEC, ii = idx - pix * LVEC;
          g_ctsM[ii * NPIX + pix]    = c[0];
          g_ctsInvM[ii * NPIX + pix] = inv; }
    } else if (gid < PREP_C_END) {
        // C: per-pixel ct0^(2^j) table, j = 0..19
        int pix = gid - PREP_B_END;
        unsigned v = mm((unsigned)ld_int(ct0, pix, lay), R2M);
#pragma unroll
        for (int j = 0; j < 20; j++) {
            g_c0pow[j * NPIX + pix] = v;
            v = mm(v, v);
        }
    }
}

// ---------------------------------------------------------------------------
// K1: IPFE decrypt + dlog + bn1 + relu.  128 blocks x 392 thr = one wave.
// ---------------------------------------------------------------------------
__global__ void __launch_bounds__(392)
k_decrypt(const void* ct0, const void* y, const void* sky,
          const float* __restrict__ bias1,
          const float* __restrict__ bg, const float* __restrict__ bb,
          const float* __restrict__ bm, const float* __restrict__ bv) {
    int gid = blockIdx.x * 392 + threadIdx.x;    // < TOTAL exactly
    int lay = detect_layout(ct0);
    int k  = gid / NPIX;
    int pj = gid - k * NPIX;

    unsigned e[LVEC], base[LVEC];
#pragma unroll
    for (int i = 0; i < LVEC; i++) {
        int yi = (int)ld_int(y, k * LVEC + i, lay);
        e[i] = (unsigned)(yi >= 0 ? yi : -yi);
        base[i] = (yi >= 0) ? g_ctsM[i * NPIX + pj] : g_ctsInvM[i * NPIX + pj];
    }
    unsigned acc = ONEM;                 // Shamir multi-exp over 6-bit |y|
#pragma unroll
    for (int bit = 5; bit >= 0; --bit) {
        acc = mm(acc, acc);
#pragma unroll
        for (int i = 0; i < LVEC; i++)
            if ((e[i] >> bit) & 1u) acc = mm(acc, base[i]);   // warp-uniform
    }
    // denominator ct0^(n-sk) from pow2 table: ~10 muls, warp-uniform bits
    unsigned sk = (unsigned)ld_int(sky, k, lay);
    unsigned E  = NN - sk;
    unsigned d  = ONEM;
#pragma unroll
    for (int j = 0; j < 20; j++)
        if ((E >> j) & 1u) d = mm(d, g_c0pow[j * NPIX + pj]);

    int ev = g_dlog[mm(acc, d)];

    float mfl = (float)ev / 10000.0f + bias1[k];
    float s = bg[k] * rsqrtf(bv[k] + 1e-5f);
    float r = (mfl - bm[k]) * s + bb[k];
    int b = pj / NPATCH, j = pj - b * NPATCH;
    g_feat1[(b * KKER + k) * NPATCH + j] = fmaxf(r, 0.0f);
}

// ---------------------------------------------------------------------------
// K2: pool1 + conv2(16->32) + bn2 + relu + pool -> g_x2.  128 blk x 392 thr
// ---------------------------------------------------------------------------
__global__ void __launch_bounds__(392)
k_conv2f(const float* __restrict__ w2, const float* __restrict__ b2,
         const float* __restrict__ bg, const float* __restrict__ bb,
         const float* __restrict__ bm, const float* __restrict__ bv) {
    __shared__ float xs[16 * 196];
    __shared__ float ws[144];
    __shared__ float part[2 * 196];
    __shared__ float pre[196];
    int b = blockIdx.x >> 5;
    int o = blockIdx.x & 31;
    int tid = threadIdx.x;              // 0..391
    int icg = tid / 196, pix = tid - icg * 196;
    int h = pix / 14, w = pix % 14;

#pragma unroll
    for (int c = 0; c < 8; c++) {       // pool 28x28 -> 14x14, 8 ch per group
        int ch = icg * 8 + c;
        const float* in = g_feat1 + (b * 16 + ch) * 784;
        int r0 = (2 * h) * 28 + 2 * w;
        xs[ch * 196 + pix] = fmaxf(fmaxf(in[r0], in[r0 + 1]),
                                   fmaxf(in[r0 + 28], in[r0 + 29]));
    }
    if (tid < 144) ws[tid] = w2[o * 144 + tid];
    __syncthreads();

    float acc = 0.f;
#pragma unroll
    for (int c = 0; c < 8; c++) {
        int ic = icg * 8 + c;
        const float* xp = xs + ic * 196;
        const float* wp = ws + ic * 9;
#pragma unroll
        for (int kh = 0; kh < 3; kh++) {
            int ih = h + kh - 1;
            if (ih < 0 || ih >= 14) continue;
#pragma unroll
            for (int kw = 0; kw < 3; kw++) {
                int iw = w + kw - 1;
                if (iw < 0 || iw >= 14) continue;
                acc += wp[kh * 3 + kw] * xp[ih * 14 + iw];
            }
        }
    }
    part[tid] = acc;
    __syncthreads();

    if (tid < 196) {
        float s = bg[o] * rsqrtf(bv[o] + 1e-5f);
        float v = part[tid] + part[196 + tid];
        pre[tid] = fmaxf((v + b2[o] - bm[o]) * s + bb[o], 0.0f);
    }
    __syncthreads();

    if (tid < 49) {
        int py = tid / 7, px = tid % 7;
        int r0 = (2 * py) * 14 + 2 * px;
        g_x2[(b * 32 + o) * 49 + tid] =
            fmaxf(fmaxf(pre[r0], pre[r0 + 1]), fmaxf(pre[r0 + 14], pre[r0 + 15]));
    }
}

// ---------------------------------------------------------------------------
// K3: conv3(32->64) + bn3 + relu + pool -> g_x3, 256 blk x 392 thr, 8-way ic.
// The LAST block to finish (atomic ticket) also runs fc1+fc2 -> out,
// saving a kernel launch.  Counter is reset for graph-replay determinism.
// ---------------------------------------------------------------------------
__global__ void __launch_bounds__(392)
k_conv3f(const float* __restrict__ w3, const float* __restrict__ b3,
         const float* __restrict__ bg, const float* __restrict__ bb,
         const float* __restrict__ bm, const float* __restrict__ bv,
         const float* __restrict__ f1w, const float* __restrict__ f1b,
         const float* __restrict__ f2w, const float* __restrict__ f2b,
         float* __restrict__ out) {
    __shared__ float xs[32 * 49];
    __shared__ float ws[288];
    __shared__ float part[392];
    __shared__ float pre[49];
    __shared__ int   s_isfc;
    __shared__ __align__(16) float xf[BATCH * 576];   // fc input (all images)
    __shared__ float hs[BATCH * 128];                 // fc1 activations
    int b = blockIdx.x >> 6;
    int o = blockIdx.x & 63;
    int tid = threadIdx.x;              // 0..391
    int icg = tid / 49, pix = tid - icg * 49;
    int h = pix / 7, w = pix % 7;

#pragma unroll
    for (int r = 0; r < 4; r++) {
        int idx = r * 392 + tid;        // 4*392 = 1568 = 32*49
        xs[idx] = g_x2[b * 1568 + idx];
    }
    if (tid < 288) ws[tid] = w3[o * 288 + tid];
    __syncthreads();

    float acc = 0.f;
#pragma unroll
    for (int c = 0; c < 4; c++) {       // 4 input channels per icg (8x4=32)
        int ic = icg * 4 + c;
        const float* xp = xs + ic * 49;
        const float* wp = ws + ic * 9;
#pragma unroll
        for (int kh = 0; kh < 3; kh++) {
            int ih = h + kh - 1;
            if (ih < 0 || ih >= 7) continue;
#pragma unroll
            for (int kw = 0; kw < 3; kw++) {
                int iw = w + kw - 1;
                if (iw < 0 || iw >= 7) continue;
                acc += wp[kh * 3 + kw] * xp[ih * 7 + iw];
            }
        }
    }
    part[tid] = acc;
    __syncthreads();

    if (tid < 49) {
        float v = ((part[tid] + part[49 + tid]) + (part[98 + tid] + part[147 + tid]))
                + ((part[196 + tid] + part[245 + tid]) + (part[294 + tid] + part[343 + tid]));
        float s = bg[o] * rsqrtf(bv[o] + 1e-5f);
        pre[tid] = fmaxf((v + b3[o] - bm[o]) * s + bb[o], 0.0f);
    }
    __syncthreads();

    if (tid < 9) {
        int py = tid / 3, px = tid % 3;
        int r0 = (2 * py) * 7 + 2 * px;
        g_x3[(b * 64 + o) * 9 + tid] =
            fmaxf(fmaxf(pre[r0], pre[r0 + 1]), fmaxf(pre[r0 + 7], pre[r0 + 8]));
        __threadfence();                // publish this block's slice (release)
    }
    __syncthreads();

    if (tid == 0) {
        unsigned ticket = atomicAdd(&g_done, 1u);
        s_isfc = (ticket == 255u);      // last arrival sees ALL slices
    }
    __syncthreads();
    if (!s_isfc) return;

    // ---------------- fc tail: fc1(576->128)+relu, fc2(128->10) ----------
    __threadfence();                    // acquire: order reads after tickets
    for (int i = tid; i < BATCH * 144; i += 392)
        ((float4*)xf)[i] = ((const float4*)g_x3)[i];
    __syncthreads();

    // fc1: 512 outputs over 392 threads (threads 0..255 take 2 outputs)
    for (int idx = tid; idx < BATCH * 128; idx += 392) {
        int bb2 = idx >> 7, oo = idx & 127;
        const float4* wr = (const float4*)(f1w + oo * 576);
        const float4* xr = (const float4*)(xf + bb2 * 576);
        float s0 = 0.f, s1 = 0.f, s2 = 0.f, s3 = 0.f;
#pragma unroll 4
        for (int i = 0; i < 144; i++) {
            float4 wv = wr[i];
            float4 xv = xr[i];
            s0 += wv.x * xv.x; s1 += wv.y * xv.y;
            s2 += wv.z * xv.z; s3 += wv.w * xv.w;
        }
        hs[idx] = fmaxf((s0 + s1) + (s2 + s3) + f1b[oo], 0.0f);
    }
    __syncthreads();

    if (tid < BATCH * 10) {
        int bb2 = tid / 10, oo = tid - bb2 * 10;
        const float* wrow = f2w + oo * 128;
        const float* hr   = hs + bb2 * 128;
        float s = 0.f;
#pragma unroll 8
        for (int i = 0; i < 128; i++) s += wrow[i] * hr[i];
        out[bb2 * 10 + oo] = s + f2b[oo];
    }
    __syncthreads();
    if (tid == 0) g_done = 0;           // reset for next graph replay
}

// ---------------------------------------------------------------------------
// Launcher. Input order (setup_inputs dict order):
// 0 ct0, 1 cts, 2 y, 3 sk_y, 4 bias1, 5-8 bn1 g/b/m/v, 9 conv2_w, 10 conv2_b,
// 11-14 bn2, 15 conv3_w, 16 conv3_b, 17-20 bn3, 21 fc1_w, 22 fc1_b,
// 23 fc2_w, 24 fc2_b, 25 g, 26 p
// ---------------------------------------------------------------------------
extern "C" void kernel_launch(void* const* d_in, const int* in_sizes, int n_in,
                              void* d_out, int out_size) {
    (void)in_sizes; (void)n_in; (void)out_size;
    const void* ct0 = d_in[0];
    const void* cts = d_in[1];
    const void* y   = d_in[2];
    const void* sky = d_in[3];
    const float* bias1 = (const float*)d_in[4];
    const float* bn1g = (const float*)d_in[5],  *bn1b = (const float*)d_in[6];
    const float* bn1m = (const float*)d_in[7],  *bn1v = (const float*)d_in[8];
    const float* c2w  = (const float*)d_in[9],  *c2b  = (const float*)d_in[10];
    const float* bn2g = (const float*)d_in[11], *bn2b = (const float*)d_in[12];
    const float* bn2m = (const float*)d_in[13], *bn2v = (const float*)d_in[14];
    const float* c3w  = (const float*)d_in[15], *c3b  = (const float*)d_in[16];
    const float* bn3g = (const float*)d_in[17], *bn3b = (const float*)d_in[18];
    const float* bn3m = (const float*)d_in[19], *bn3v = (const float*)d_in[20];
    const float* f1w  = (const float*)d_in[21], *f1b  = (const float*)d_in[22];
    const float* f2w  = (const float*)d_in[23], *f2b  = (const float*)d_in[24];
    const void* gptr  = d_in[25];
    float* out = (float*)d_out;

    k_prep   <<<(PREP_C_END + 255) / 256, 256>>>(ct0, cts, gptr);
    k_decrypt<<<128, 392>>>(ct0, y, sky, bias1, bn1g, bn1b, bn1m, bn1v);
    k_conv2f <<<128, 392>>>(c2w, c2b, bn2g, bn2b, bn2m, bn2v);
    k_conv3f <<<256, 392>>>(c3w, c3b, bn3g, bn3b, bn3m, bn3v,
                            f1w, f1b, f2w, f2b, out);
}

// round 16
// speedup vs baseline: 1.9041x; 1.9041x over previous
#include <cuda_runtime.h>
#include <math.h>

// ---------------------------------------------------------------------------
// Problem constants (fixed by the dataset generator)
// ---------------------------------------------------------------------------
#define PP   1000003u          // prime modulus
#define NN   1000002u          // group order p-1 = 2*3*166667
#define BATCH 4
#define NPATCH 784
#define LVEC 9
#define KKER 16
#define NPIX (BATCH * NPATCH)        // 3136
#define TOTAL (KKER * NPIX)          // 50176
#define DRANGE 9000
#define TSIZE (2 * DRANGE + 1)       // 18001

// prep work partition (thread-id ranges)
#define TCHUNKS ((TSIZE + 7) / 8)            // 2251 dlog-chain threads
#define CCHUNKS (NPIX * LVEC / 8)            // 3528 cts batch-inverse threads
#define PREP_B_END (TCHUNKS + CCHUNKS)       // 5779
#define PREP_C_END (PREP_B_END + NPIX)       // 8915

// ---------------------------------------------------------------------------
// Montgomery constants (compile time)
// ---------------------------------------------------------------------------
constexpr unsigned nprime_f() {            // -p^{-1} mod 2^32 (Newton)
    unsigned inv = PP;
    for (int i = 0; i < 5; i++) inv *= 2u - PP * inv;
    return 0u - inv;
}
constexpr unsigned onem_f() { return (unsigned)((1ULL << 32) % PP); }
constexpr unsigned r2_f() {
    return (unsigned)(((unsigned long long)onem_f() * onem_f()) % PP);
}
constexpr unsigned NPRIME = nprime_f();
constexpr unsigned ONEM   = onem_f();
constexpr unsigned R2M    = r2_f();

// ---------------------------------------------------------------------------
// Scratch (device globals; no dynamic allocation anywhere)
// ---------------------------------------------------------------------------
__device__ int      g_dlog[1000003];
__device__ unsigned g_ctsM[LVEC * NPIX];
__device__ unsigned g_ctsInvM[LVEC * NPIX];
__device__ unsigned g_c0pow[20 * NPIX];          // ct0^(2^j), [j][pixel]
__device__ __align__(16) float g_feat1[BATCH * KKER * NPATCH];
__device__ __align__(16) float g_x2[BATCH * 32 * 7 * 7];
__device__ __align__(16) float g_x3[BATCH * 64 * 3 * 3];

// ---------------------------------------------------------------------------
// Montgomery multiply: a,b in Mont domain (< p); result < p.
// ---------------------------------------------------------------------------
__device__ __forceinline__ unsigned mm(unsigned a, unsigned b) {
    unsigned long long T = (unsigned long long)a * b;
    unsigned m = (unsigned)T * NPRIME;
    unsigned long long t = (T + (unsigned long long)m * PP) >> 32;
    unsigned r = (unsigned)t;
    return (r >= PP) ? r - PP : r;
}

__device__ __forceinline__ unsigned powM(unsigned b, unsigned e) {
    unsigned r = ONEM;
    while (e) {
        if (e & 1u) r = mm(r, b);
        b = mm(b, b);
        e >>= 1;
    }
    return r;
}

__device__ __forceinline__ unsigned powM20(unsigned b, unsigned e) {
    unsigned r = ONEM;
#pragma unroll
    for (int i = 0; i < 20; i++) {
        if ((e >> i) & 1u) r = mm(r, b);
        b = mm(b, b);
    }
    return r;
}

// ---------------------------------------------------------------------------
// Input layout detection (int32 / int64 / float32), from ct0 buffer.
// ---------------------------------------------------------------------------
__device__ __forceinline__ int detect_layout(const void* ct0) {
    const unsigned* u = (const unsigned*)ct0;
    unsigned w0 = u[0];
    if (w0 >= 1u && w0 < PP) {
        if (u[1] == 0u && u[3] == 0u && u[5] == 0u) return 1;  // int64
        return 0;                                              // int32
    }
    return 2;                                                  // float32
}

__device__ __forceinline__ long long ld_int(const void* ptr, int idx, int lay) {
    if (lay == 0) return (long long)((const int*)ptr)[idx];
    if (lay == 1) return ((const long long*)ptr)[idx];
    return (long long)llrintf(((const float*)ptr)[idx]);
}

// ---------------------------------------------------------------------------
// K0: prep — chained dlog table + batch-inverted Mont cts + ct0 pow2 table
// ---------------------------------------------------------------------------
__global__ void k_prep(const void* ct0, const void* cts, const void* gptr) {
    int gid = blockIdx.x * blockDim.x + threadIdx.x;
    int lay = detect_layout(ct0);
    if (gid < TCHUNKS) {
        // A: dlog table, 8 chained entries per thread (1 pow + 7 muls)
        unsigned g  = (unsigned)ld_int(gptr, 0, lay) % PP;
        unsigned gM = mm(g, R2M);
        int te0 = gid * 8;
        int e0  = te0 - DRANGE;
        unsigned ee = (e0 < 0) ? (unsigned)(e0 + (int)NN) : (unsigned)e0;
        unsigned v = powM(gM, ee);
#pragma unroll
        for (int j = 0; j < 8; j++) {
            int te = te0 + j;
            if (te < TSIZE) g_dlog[v] = te - DRANGE;
            v = mm(v, gM);
        }
    } else if (gid < PREP_B_END) {
        // B: cts -> Mont + batch inversion (Montgomery trick), 8 per thread
        int i0 = (gid - TCHUNKS) * 8;
        unsigned c[8], pfx[8];
#pragma unroll
        for (int j = 0; j < 8; j++)
            c[j] = mm((unsigned)ld_int(cts, i0 + j, lay), R2M);
        pfx[0] = c[0];
#pragma unroll
        for (int j = 1; j < 8; j++) pfx[j] = mm(pfx[j - 1], c[j]);
        unsigned inv = powM20(pfx[7], PP - 2u);      // one Fermat for 8 items
#pragma unroll
        for (int j = 7; j >= 1; j--) {
            unsigned invj = mm(inv, pfx[j - 1]);
            inv = mm(inv, c[j]);
            int idx = i0 + j, pix = idx / LVEC, ii = idx - pix * LVEC;
            g_ctsM[ii * NPIX + pix]    = c[j];
            g_ctsInvM[ii * NPIX + pix] = invj;
        }
        { int idx = i0, pix = idx / LVEC, ii = idx - pix * LVEC;
          g_ctsM[ii * NPIX + pix]    = c[0];
          g_ctsInvM[ii * NPIX + pix] = inv; }
    } else if (gid < PREP_C_END) {
        // C: per-pixel ct0^(2^j) table, j = 0..19
        int pix = gid - PREP_B_END;
        unsigned v = mm((unsigned)ld_int(ct0, pix, lay), R2M);
#pragma unroll
        for (int j = 0; j < 20; j++) {
            g_c0pow[j * NPIX + pix] = v;
            v = mm(v, v);
        }
    }
}

// ---------------------------------------------------------------------------
// K1: IPFE decrypt + dlog + bn1 + relu.  128 blocks x 392 thr = one wave.
// ---------------------------------------------------------------------------
__global__ void __launch_bounds__(392)
k_decrypt(const void* ct0, const void* y, const void* sky,
          const float* __restrict__ bias1,
          const float* __restrict__ bg, const float* __restrict__ bb,
          const float* __restrict__ bm, const float* __restrict__ bv) {
    int gid = blockIdx.x * 392 + threadIdx.x;    // < TOTAL exactly
    int lay = detect_layout(ct0);
    int k  = gid / NPIX;
    int pj = gid - k * NPIX;

    unsigned e[LVEC], base[LVEC];
#pragma unroll
    for (int i = 0; i < LVEC; i++) {
        int yi = (int)ld_int(y, k * LVEC + i, lay);
        e[i] = (unsigned)(yi >= 0 ? yi : -yi);
        base[i] = (yi >= 0) ? g_ctsM[i * NPIX + pj] : g_ctsInvM[i * NPIX + pj];
    }
    unsigned acc = ONEM;                 // Shamir multi-exp over 6-bit |y|
#pragma unroll
    for (int bit = 5; bit >= 0; --bit) {
        acc = mm(acc, acc);
#pragma unroll
        for (int i = 0; i < LVEC; i++)
            if ((e[i] >> bit) & 1u) acc = mm(acc, base[i]);   // warp-uniform
    }
    // denominator ct0^(n-sk) from pow2 table: ~10 muls, warp-uniform bits
    unsigned sk = (unsigned)ld_int(sky, k, lay);
    unsigned E  = NN - sk;
    unsigned d  = ONEM;
#pragma unroll
    for (int j = 0; j < 20; j++)
        if ((E >> j) & 1u) d = mm(d, g_c0pow[j * NPIX + pj]);

    int ev = g_dlog[mm(acc, d)];

    float mfl = (float)ev / 10000.0f + bias1[k];
    float s = bg[k] * rsqrtf(bv[k] + 1e-5f);
    float r = (mfl - bm[k]) * s + bb[k];
    int b = pj / NPATCH, j = pj - b * NPATCH;
    g_feat1[(b * KKER + k) * NPATCH + j] = fmaxf(r, 0.0f);
}

// ---------------------------------------------------------------------------
// K2: pool1 + conv2(16->32) + bn2 + relu + pool -> g_x2.  128 blk x 392 thr
// ---------------------------------------------------------------------------
__global__ void __launch_bounds__(392)
k_conv2f(const float* __restrict__ w2, const float* __restrict__ b2,
         const float* __restrict__ bg, const float* __restrict__ bb,
         const float* __restrict__ bm, const float* __restrict__ bv) {
    __shared__ float xs[16 * 196];
    __shared__ float ws[144];
    __shared__ float part[2 * 196];
    __shared__ float pre[196];
    int b = blockIdx.x >> 5;
    int o = blockIdx.x & 31;
    int tid = threadIdx.x;              // 0..391
    int icg = tid / 196, pix = tid - icg * 196;
    int h = pix / 14, w = pix % 14;

#pragma unroll
    for (int c = 0; c < 8; c++) {       // pool 28x28 -> 14x14, 8 ch per group
        int ch = icg * 8 + c;
        const float* in = g_feat1 + (b * 16 + ch) * 784;
        int r0 = (2 * h) * 28 + 2 * w;
        xs[ch * 196 + pix] = fmaxf(fmaxf(in[r0], in[r0 + 1]),
                                   fmaxf(in[r0 + 28], in[r0 + 29]));
    }
    if (tid < 144) ws[tid] = w2[o * 144 + tid];
    __syncthreads();

    float acc = 0.f;
#pragma unroll
    for (int c = 0; c < 8; c++) {
        int ic = icg * 8 + c;
        const float* xp = xs + ic * 196;
        const float* wp = ws + ic * 9;
#pragma unroll
        for (int kh = 0; kh < 3; kh++) {
            int ih = h + kh - 1;
            if (ih < 0 || ih >= 14) continue;
#pragma unroll
            for (int kw = 0; kw < 3; kw++) {
                int iw = w + kw - 1;
                if (iw < 0 || iw >= 14) continue;
                acc += wp[kh * 3 + kw] * xp[ih * 14 + iw];
            }
        }
    }
    part[tid] = acc;
    __syncthreads();

    if (tid < 196) {
        float s = bg[o] * rsqrtf(bv[o] + 1e-5f);
        float v = part[tid] + part[196 + tid];
        pre[tid] = fmaxf((v + b2[o] - bm[o]) * s + bb[o], 0.0f);
    }
    __syncthreads();

    if (tid < 49) {
        int py = tid / 7, px = tid % 7;
        int r0 = (2 * py) * 14 + 2 * px;
        g_x2[(b * 32 + o) * 49 + tid] =
            fmaxf(fmaxf(pre[r0], pre[r0 + 1]), fmaxf(pre[r0 + 14], pre[r0 + 15]));
    }
}

// ---------------------------------------------------------------------------
// K3: conv3(32->64) + bn3 + relu + pool -> g_x3.  256 blk x 392 thr, 8-way ic
// ---------------------------------------------------------------------------
__global__ void __launch_bounds__(392)
k_conv3f(const float* __restrict__ w3, const float* __restrict__ b3,
         const float* __restrict__ bg, const float* __restrict__ bb,
         const float* __restrict__ bm, const float* __restrict__ bv) {
    __shared__ float xs[32 * 49];
    __shared__ float ws[288];
    __shared__ float part[392];
    __shared__ float pre[49];
    int b = blockIdx.x >> 6;
    int o = blockIdx.x & 63;
    int tid = threadIdx.x;              // 0..391
    int icg = tid / 49, pix = tid - icg * 49;
    int h = pix / 7, w = pix % 7;

#pragma unroll
    for (int r = 0; r < 4; r++) {
        int idx = r * 392 + tid;        // 4*392 = 1568 = 32*49
        xs[idx] = g_x2[b * 1568 + idx];
    }
    if (tid < 288) ws[tid] = w3[o * 288 + tid];
    __syncthreads();

    float acc = 0.f;
#pragma unroll
    for (int c = 0; c < 4; c++) {       // 4 input channels per icg (8x4=32)
        int ic = icg * 4 + c;
        const float* xp = xs + ic * 49;
        const float* wp = ws + ic * 9;
#pragma unroll
        for (int kh = 0; kh < 3; kh++) {
            int ih = h + kh - 1;
            if (ih < 0 || ih >= 7) continue;
#pragma unroll
            for (int kw = 0; kw < 3; kw++) {
                int iw = w + kw - 1;
                if (iw < 0 || iw >= 7) continue;
                acc += wp[kh * 3 + kw] * xp[ih * 7 + iw];
            }
        }
    }
    part[tid] = acc;
    __syncthreads();

    if (tid < 49) {
        float v = ((part[tid] + part[49 + tid]) + (part[98 + tid] + part[147 + tid]))
                + ((part[196 + tid] + part[245 + tid]) + (part[294 + tid] + part[343 + tid]));
        float s = bg[o] * rsqrtf(bv[o] + 1e-5f);
        pre[tid] = fmaxf((v + b3[o] - bm[o]) * s + bb[o], 0.0f);
    }
    __syncthreads();

    if (tid < 9) {
        int py = tid / 3, px = tid % 3;
        int r0 = (2 * py) * 7 + 2 * px;
        g_x3[(b * 64 + o) * 9 + tid] =
            fmaxf(fmaxf(pre[r0], pre[r0 + 1]), fmaxf(pre[r0 + 7], pre[r0 + 8]));
    }
}

// ---------------------------------------------------------------------------
// K4: fused fc1(576->128)+relu and fc2(128->10).  4 blocks x 128 threads.
// ---------------------------------------------------------------------------
__global__ void k_fc(const float* __restrict__ w1, const float* __restrict__ b1,
                     const float* __restrict__ w2, const float* __restrict__ b2,
                     float* __restrict__ out) {
    __shared__ __align__(16) float xs[576];
    __shared__ float hs[128];
    int b = blockIdx.x;
    int tid = threadIdx.x;              // 0..127

    for (int i = tid; i < 144; i += 128)
        ((float4*)xs)[i] = ((const float4*)(g_x3 + b * 576))[i];
    __syncthreads();

    const float4* wr = (const float4*)(w1 + tid * 576);
    float s0 = 0.f, s1 = 0.f, s2 = 0.f, s3 = 0.f;
#pragma unroll 4
    for (int i = 0; i < 144; i++) {
        float4 wv = wr[i];
        float4 xv = ((float4*)xs)[i];
        s0 += wv.x * xv.x; s1 += wv.y * xv.y;
        s2 += wv.z * xv.z; s3 += wv.w * xv.w;
    }
    hs[tid] = fmaxf((s0 + s1) + (s2 + s3) + b1[tid], 0.0f);
    __syncthreads();

    if (tid < 10) {
        const float* wrow = w2 + tid * 128;
        float s = 0.f;
#pragma unroll 8
        for (int i = 0; i < 128; i++) s += wrow[i] * hs[i];
        out[b * 10 + tid] = s + b2[tid];
    }
}

// ---------------------------------------------------------------------------
// Launcher. Input order (setup_inputs dict order):
// 0 ct0, 1 cts, 2 y, 3 sk_y, 4 bias1, 5-8 bn1 g/b/m/v, 9 conv2_w, 10 conv2_b,
// 11-14 bn2, 15 conv3_w, 16 conv3_b, 17-20 bn3, 21 fc1_w, 22 fc1_b,
// 23 fc2_w, 24 fc2_b, 25 g, 26 p
// ---------------------------------------------------------------------------
extern "C" void kernel_launch(void* const* d_in, const int* in_sizes, int n_in,
                              void* d_out, int out_size) {
    (void)in_sizes; (void)n_in; (void)out_size;
    const void* ct0 = d_in[0];
    const void* cts = d_in[1];
    const void* y   = d_in[2];
    const void* sky = d_in[3];
    const float* bias1 = (const float*)d_in[4];
    const float* bn1g = (const float*)d_in[5],  *bn1b = (const float*)d_in[6];
    const float* bn1m = (const float*)d_in[7],  *bn1v = (const float*)d_in[8];
    const float* c2w  = (const float*)d_in[9],  *c2b  = (const float*)d_in[10];
    const float* bn2g = (const float*)d_in[11], *bn2b = (const float*)d_in[12];
    const float* bn2m = (const float*)d_in[13], *bn2v = (const float*)d_in[14];
    const float* c3w  = (const float*)d_in[15], *c3b  = (const float*)d_in[16];
    const float* bn3g = (const float*)d_in[17], *bn3b = (const float*)d_in[18];
    const float* bn3m = (const float*)d_in[19], *bn3v = (const float*)d_in[20];
    const float* f1w  = (const float*)d_in[21], *f1b  = (const float*)d_in[22];
    const float* f2w  = (const float*)d_in[23], *f2b  = (const float*)d_in[24];
    const void* gptr  = d_in[25];
    float* out = (float*)d_out;

    k_prep   <<<(PREP_C_END + 255) / 256, 256>>>(ct0, cts, gptr);
    k_decrypt<<<128, 392>>>(ct0, y, sky, bias1, bn1g, bn1b, bn1m, bn1v);
    k_conv2f <<<128, 392>>>(c2w, c2b, bn2g, bn2b, bn2m, bn2v);
    k_conv3f <<<256, 392>>>(c3w, c3b, bn3g, bn3b, bn3m, bn3v);
    k_fc     <<<4, 128>>>(f1w, f1b, f2w, f2b, out);
}